// round 1
// baseline (speedup 1.0000x reference)
#include <cuda_runtime.h>
#include <math.h>

#define BB 32
#define TT 1500
#define HH 768
#define HM1 767
#define LQ 400
#define MM (BB*LQ)            /* 12800 */
#define FC_OFF ((size_t)MM*HH)     /* 9830400 */
#define NHAT_OFF ((size_t)2*MM*HH) /* 19660800 */
#define P_MIX_C 0.15f

// Scratch (allocation-free rule: static __device__ globals)
__device__ float g_scale[BB];
__device__ float g_nhat_part[BB];
__device__ float g_sa[(size_t)MM * HH];   // s_a padded to K=768, col 767 = 0
__device__ float g_y1[(size_t)MM * HH];   // relu(s_a@W1+b1)

// ---------------------------------------------------------------------------
// Kernel 1: per-batch alpha sum over T=1500, scale, n_hat partial
// ---------------------------------------------------------------------------
__global__ void alpha_kernel(const float* __restrict__ hs,
                             const int* __restrict__ lengths) {
    int b = blockIdx.x;
    const float* base = hs + (size_t)b * TT * HH + (HH - 1);
    float s = 0.f;
    for (int t = threadIdx.x; t < TT; t += blockDim.x) {
        float x = base[(size_t)t * HH];
        s += 1.f / (1.f + expf(-x));
    }
    __shared__ float red[256];
    red[threadIdx.x] = s;
    __syncthreads();
    for (int o = 128; o > 0; o >>= 1) {
        if (threadIdx.x < o) red[threadIdx.x] += red[threadIdx.x + o];
        __syncthreads();
    }
    if (threadIdx.x == 0) {
        float sum = red[0];
        int li = lengths[b];
        float tll = (float)(li < LQ ? li : LQ);
        g_scale[b] = tll / sum;
        float d = tll - sum;
        g_nhat_part[b] = d * d;
    }
}

__global__ void nhat_kernel(float* __restrict__ out) {
    float v = g_nhat_part[threadIdx.x];
    #pragma unroll
    for (int o = 16; o > 0; o >>= 1) v += __shfl_down_sync(0xffffffffu, v, o);
    if (threadIdx.x == 0) out[0] = v;
}

// ---------------------------------------------------------------------------
// Kernel 2: CIF scan. grid (3, B), 256 threads. One thread per feature lane;
// scalar carry a_r recomputed redundantly per thread (no communication).
// Feature 767 (pad lane) gets h=0 -> writes zeros (pads s_a to K=768).
// ---------------------------------------------------------------------------
__global__ void cif_scan_kernel(const float* __restrict__ hs) {
    int b = blockIdx.y;
    int f = blockIdx.x * blockDim.x + threadIdx.x;   // 0..767
    __shared__ float s_alpha[LQ];
    float scale = g_scale[b];
    const float* hb = hs + (size_t)b * TT * HH;
    for (int t = threadIdx.x; t < LQ; t += blockDim.x) {
        float x = hb[(size_t)t * HH + (HH - 1)];
        s_alpha[t] = scale / (1.f + expf(-x));
    }
    __syncthreads();

    bool valid = (f < HM1);
    const float* hcol = hb + f;
    float* out = g_sa + (size_t)b * LQ * HH + f;

    float a_r = 0.f, s_r = 0.f;
    float h = valid ? hcol[0] : 0.f;
    for (int t = 0; t < LQ; ++t) {
        // prefetch next h (row t+1 exists: t+1 <= 400 < 1500)
        float hn = valid ? hcol[(size_t)(t + 1) * HH] : 0.f;
        float a = s_alpha[t];
        float a_a = a + a_r;
        float rem = 1.0f - a_r;
        float s_a_nf = s_r + a * h;
        float s_a;
        if (a_a >= 1.0f) {
            float a_r_f = a - rem;
            s_a = s_r + rem * h;
            a_r = a_r_f;
            s_r = a_r_f * h;
        } else {
            a_r = a_a;
            s_a = s_a_nf;
            s_r = s_a_nf;
        }
        out[(size_t)t * HH] = s_a;
        h = hn;
    }
}

// ---------------------------------------------------------------------------
// Kernel 3: SGEMM 128x128x8, 256 threads, 8x8 microtile.
// C[M=12800, N=768] = A[M,768] @ Bm[Kvalid,768] + bias ; optional relu,
// optional mix epilogue (writes bert_mixing + fc).
// ---------------------------------------------------------------------------
template <int RELU, int MIX>
__global__ void __launch_bounds__(256)
sgemm_kernel(const float* __restrict__ A, const float* __restrict__ Bm,
             const float* __restrict__ bias, float* __restrict__ Cout,
             const float* __restrict__ bert, const float* __restrict__ mixu,
             float* __restrict__ fcout, int Kvalid) {
    __shared__ float As[8][128];
    __shared__ float Bs[8][128];

    int tid = threadIdx.x;
    int row0 = blockIdx.y * 128;
    int col0 = blockIdx.x * 128;

    int arow = tid >> 1;               // 0..127
    int acol = (tid & 1) * 4;          // 0 or 4
    int brow = tid >> 5;               // 0..7
    int bcol = (tid & 31) * 4;         // 0..124

    const float* Aptr = A + (size_t)(row0 + arow) * HH + acol;
    const float* Bbase = Bm + col0 + bcol;

    int tx = tid & 15;                 // col group
    int ty = tid >> 4;                 // row group

    float acc[8][8];
    #pragma unroll
    for (int i = 0; i < 8; ++i)
        #pragma unroll
        for (int j = 0; j < 8; ++j) acc[i][j] = 0.f;

    for (int k0 = 0; k0 < HH; k0 += 8) {
        float4 av = *(const float4*)(Aptr + k0);
        float4 bv;
        int kb = k0 + brow;
        if (kb < Kvalid) bv = *(const float4*)(Bbase + (size_t)kb * HH);
        else             bv = make_float4(0.f, 0.f, 0.f, 0.f);

        As[acol + 0][arow] = av.x;
        As[acol + 1][arow] = av.y;
        As[acol + 2][arow] = av.z;
        As[acol + 3][arow] = av.w;
        *(float4*)&Bs[brow][bcol] = bv;
        __syncthreads();

        #pragma unroll
        for (int kk = 0; kk < 8; ++kk) {
            float4 a0 = *(const float4*)&As[kk][ty * 8];
            float4 a1 = *(const float4*)&As[kk][ty * 8 + 4];
            float4 b0 = *(const float4*)&Bs[kk][tx * 8];
            float4 b1 = *(const float4*)&Bs[kk][tx * 8 + 4];
            float ar[8] = {a0.x, a0.y, a0.z, a0.w, a1.x, a1.y, a1.z, a1.w};
            float br[8] = {b0.x, b0.y, b0.z, b0.w, b1.x, b1.y, b1.z, b1.w};
            #pragma unroll
            for (int i = 0; i < 8; ++i)
                #pragma unroll
                for (int j = 0; j < 8; ++j)
                    acc[i][j] = fmaf(ar[i], br[j], acc[i][j]);
        }
        __syncthreads();
    }

    // Epilogue
    #pragma unroll
    for (int i = 0; i < 8; ++i) {
        int row = row0 + ty * 8 + i;
        float mflag = 0.f;
        if (MIX) mflag = (mixu[row] < P_MIX_C) ? 1.f : 0.f;
        #pragma unroll
        for (int j = 0; j < 8; ++j) {
            int col = col0 + tx * 8 + j;
            float v = acc[i][j] + bias[col];
            if (RELU) v = fmaxf(v, 0.f);
            size_t idx = (size_t)row * HH + col;
            if (MIX) {
                float bm = (mflag != 0.f) ? bert[idx] : v;
                Cout[idx] = bm;     // bert_mixing region
                fcout[idx] = v;     // fc region
            } else {
                Cout[idx] = v;
            }
        }
    }
}

// ---------------------------------------------------------------------------
extern "C" void kernel_launch(void* const* d_in, const int* in_sizes, int n_in,
                              void* d_out, int out_size) {
    const float* hs      = (const float*)d_in[0];
    const int*   lengths = (const int*)  d_in[1];
    const float* W1      = (const float*)d_in[2];
    const float* b1      = (const float*)d_in[3];
    const float* W2      = (const float*)d_in[4];
    const float* b2      = (const float*)d_in[5];
    const float* bert    = (const float*)d_in[6];
    const float* mixu    = (const float*)d_in[7];
    float* out = (float*)d_out;

    float* g_sa_p;  cudaGetSymbolAddress((void**)&g_sa_p, g_sa);
    float* g_y1_p;  cudaGetSymbolAddress((void**)&g_y1_p, g_y1);

    alpha_kernel<<<BB, 256>>>(hs, lengths);
    nhat_kernel<<<1, 32>>>(out + NHAT_OFF);
    cif_scan_kernel<<<dim3(3, BB), 256>>>(hs);

    // GEMM1: y1 = relu(s_a @ W1 + b1), K valid = 767 (row 767 of W1 absent)
    sgemm_kernel<1, 0><<<dim3(6, 100), 256>>>(
        g_sa_p, W1, b1, g_y1_p, nullptr, nullptr, nullptr, HM1);

    // GEMM2: fc = y1 @ W2 + b2 ; fused mixing epilogue writes both outputs
    sgemm_kernel<0, 1><<<dim3(6, 100), 256>>>(
        g_y1_p, W2, b2, out /*bert_mixing*/, bert, mixu,
        out + FC_OFF /*fc*/, HH);
}

// round 3
// speedup vs baseline: 2.7963x; 2.7963x over previous
#include <cuda_runtime.h>
#include <cuda_bf16.h>
#include <math.h>
#include <stdint.h>

#define BB 32
#define TT 1500
#define HH 768
#define HM1 767
#define LQ 400
#define MM (BB*LQ)                 /* 12800 */
#define FC_OFF ((size_t)MM*HH)
#define NHAT_OFF ((size_t)2*MM*HH)
#define P_MIX_C 0.15f

// ---------------- scratch (__device__ globals, no allocs) ------------------
__device__ float g_scale[BB];
__device__ float g_nhat_part[BB];
__device__ __nv_bfloat16 g_sa_hi[(size_t)MM * HH];
__device__ __nv_bfloat16 g_sa_lo[(size_t)MM * HH];
__device__ __nv_bfloat16 g_y1_hi[(size_t)MM * HH];
__device__ __nv_bfloat16 g_y1_lo[(size_t)MM * HH];
__device__ __nv_bfloat16 g_w1t_hi[(size_t)HH * HH];
__device__ __nv_bfloat16 g_w1t_lo[(size_t)HH * HH];
__device__ __nv_bfloat16 g_w2t_hi[(size_t)HH * HH];
__device__ __nv_bfloat16 g_w2t_lo[(size_t)HH * HH];

// ---------------- helpers --------------------------------------------------
__device__ __forceinline__ uint32_t smem_u32(const void* p) {
    uint32_t a;
    asm("{ .reg .u64 t; cvta.to.shared.u64 t, %1; cvt.u32.u64 %0, t; }"
        : "=r"(a) : "l"(p));
    return a;
}
__device__ __forceinline__ void split_bf16(float v, __nv_bfloat16& h, __nv_bfloat16& l) {
    h = __float2bfloat16(v);
    l = __float2bfloat16(v - __bfloat162float(h));
}
__device__ __forceinline__ uint32_t pack2(__nv_bfloat16 a, __nv_bfloat16 b) {
    return (uint32_t)__bfloat16_as_ushort(a) |
           ((uint32_t)__bfloat16_as_ushort(b) << 16);
}

#define CP16(d, s) \
    asm volatile("cp.async.cg.shared.global [%0], [%1], 16;" :: "r"(d), "l"(s))
#define CP_COMMIT() asm volatile("cp.async.commit_group;" ::: "memory")
#define CP_WAIT(n)  asm volatile("cp.async.wait_group %0;" :: "n"(n) : "memory")

#define LDM4(r, addr) \
    asm volatile("ldmatrix.sync.aligned.m8n8.x4.shared.b16 {%0,%1,%2,%3},[%4];" \
        : "=r"((r)[0]), "=r"((r)[1]), "=r"((r)[2]), "=r"((r)[3]) : "r"(addr))

#define MMA(d, a, b) \
    asm volatile("mma.sync.aligned.m16n8k16.row.col.f32.bf16.bf16.f32 " \
        "{%0,%1,%2,%3},{%4,%5,%6,%7},{%8,%9},{%0,%1,%2,%3};" \
        : "+f"((d)[0]), "+f"((d)[1]), "+f"((d)[2]), "+f"((d)[3]) \
        : "r"((a)[0]), "r"((a)[1]), "r"((a)[2]), "r"((a)[3]), \
          "r"((b)[0]), "r"((b)[1]))

// ---------------------------------------------------------------------------
// Kernel 1: per-batch alpha sum, scale, n_hat partial
// ---------------------------------------------------------------------------
__global__ void alpha_kernel(const float* __restrict__ hs,
                             const int* __restrict__ lengths) {
    int b = blockIdx.x;
    const float* base = hs + (size_t)b * TT * HH + (HH - 1);
    float s = 0.f;
    for (int t = threadIdx.x; t < TT; t += blockDim.x)
        s += 1.f / (1.f + expf(-base[(size_t)t * HH]));
    __shared__ float red[256];
    red[threadIdx.x] = s;
    __syncthreads();
    for (int o = 128; o > 0; o >>= 1) {
        if (threadIdx.x < o) red[threadIdx.x] += red[threadIdx.x + o];
        __syncthreads();
    }
    if (threadIdx.x == 0) {
        float sum = red[0];
        int li = lengths[b];
        float tll = (float)(li < LQ ? li : LQ);
        g_scale[b] = tll / sum;
        float d = tll - sum;
        g_nhat_part[b] = d * d;
    }
}
__global__ void nhat_kernel(float* __restrict__ out) {
    float v = g_nhat_part[threadIdx.x];
    #pragma unroll
    for (int o = 16; o > 0; o >>= 1) v += __shfl_down_sync(0xffffffffu, v, o);
    if (threadIdx.x == 0) out[0] = v;
}

// ---------------------------------------------------------------------------
// Kernel 2: CIF scan -> hi/lo bf16 planes. Pad lane 767 -> zeros.
// ---------------------------------------------------------------------------
__global__ void cif_scan_kernel(const float* __restrict__ hs) {
    int b = blockIdx.y;
    int f = blockIdx.x * blockDim.x + threadIdx.x;   // 0..767
    __shared__ float s_alpha[LQ];
    float scale = g_scale[b];
    const float* hb = hs + (size_t)b * TT * HH;
    for (int t = threadIdx.x; t < LQ; t += blockDim.x)
        s_alpha[t] = scale / (1.f + expf(-hb[(size_t)t * HH + (HH - 1)]));
    __syncthreads();

    bool valid = (f < HM1);
    const float* hcol = hb + f;
    size_t obase = (size_t)b * LQ * HH + f;

    float a_r = 0.f, s_r = 0.f;
    float h = valid ? hcol[0] : 0.f;
    for (int t = 0; t < LQ; ++t) {
        float hn = valid ? hcol[(size_t)(t + 1) * HH] : 0.f;
        float a = s_alpha[t];
        float a_a = a + a_r;
        float rem = 1.0f - a_r;
        float s_a_nf = s_r + a * h;
        float s_a;
        if (a_a >= 1.0f) {
            float a_r_f = a - rem;
            s_a = s_r + rem * h;
            a_r = a_r_f;
            s_r = a_r_f * h;
        } else {
            a_r = a_a; s_a = s_a_nf; s_r = s_a_nf;
        }
        __nv_bfloat16 hi, lo;
        split_bf16(s_a, hi, lo);
        g_sa_hi[obase + (size_t)t * HH] = hi;
        g_sa_lo[obase + (size_t)t * HH] = lo;
        h = hn;
    }
}

// ---------------------------------------------------------------------------
// Kernel 3: W transpose + split: Wt[n][k] = split(W[k][n]), k>=Kvalid -> 0
// ---------------------------------------------------------------------------
__global__ void wtrans_kernel(const float* __restrict__ W,
                              __nv_bfloat16* __restrict__ Wt_hi,
                              __nv_bfloat16* __restrict__ Wt_lo, int Kvalid) {
    __shared__ float t[32][33];
    int n = blockIdx.x * 32 + threadIdx.x;
    #pragma unroll
    for (int j = 0; j < 32; j += 8) {
        int k = blockIdx.y * 32 + threadIdx.y + j;
        t[threadIdx.y + j][threadIdx.x] = (k < Kvalid) ? W[(size_t)k * HH + n] : 0.f;
    }
    __syncthreads();
    #pragma unroll
    for (int j = 0; j < 32; j += 8) {
        int nn = blockIdx.x * 32 + threadIdx.y + j;
        int kk = blockIdx.y * 32 + threadIdx.x;
        __nv_bfloat16 hi, lo;
        split_bf16(t[threadIdx.x][threadIdx.y + j], hi, lo);
        Wt_hi[(size_t)nn * HH + kk] = hi;
        Wt_lo[(size_t)nn * HH + kk] = lo;
    }
}

// ---------------------------------------------------------------------------
// Kernel 4: HMMA split-bf16 GEMM. CTA tile 128x128, 8 warps (2x4), warp tile
// 64x32. K chunks of 64, 2-stage cp.async pipeline, XOR-swizzled SMEM.
// MODE 0: y1 = relu(A@B^T+b) -> hi/lo planes. MODE 1: fc + bert_mixing.
// ---------------------------------------------------------------------------
#define KCH 64
#define NCHUNK (HH / KCH)            /* 12 */
#define MAT_BYTES 16384              /* 128 rows x 128B */
#define STAGE_BYTES (4 * MAT_BYTES)  /* 65536 */
#define SMEM_SZ (2 * STAGE_BYTES)    /* 131072 */

template <int MODE>
__global__ void __launch_bounds__(256, 1)
gemm_hmma(const __nv_bfloat16* __restrict__ Ahi, const __nv_bfloat16* __restrict__ Alo,
          const __nv_bfloat16* __restrict__ Bhi, const __nv_bfloat16* __restrict__ Blo,
          const float* __restrict__ bias,
          __nv_bfloat16* __restrict__ yhi, __nv_bfloat16* __restrict__ ylo,
          float* __restrict__ outbm, float* __restrict__ fcout,
          const float* __restrict__ bert, const float* __restrict__ mixu) {
    extern __shared__ char smem[];
    uint32_t sb = smem_u32(smem);
    int tid = threadIdx.x, lane = tid & 31, wid = tid >> 5;
    int row0 = blockIdx.y * 128, col0 = blockIdx.x * 128;
    int wr = wid >> 2, wc = wid & 3;     // warp: rows wr*64, cols wc*32

    float acc[4][4][4];
    #pragma unroll
    for (int i = 0; i < 4; ++i)
        #pragma unroll
        for (int j = 0; j < 4; ++j)
            #pragma unroll
            for (int d = 0; d < 4; ++d) acc[i][j][d] = 0.f;

    // copy indexing (per 16B unit)
    int cr = tid >> 3, cu = tid & 7;     // base row/unit; +32 rows per q

    // ldmatrix lane geometry
    int a_row = lane & 15;
    int a_un  = lane >> 4;               // k-half
    int b_row = (lane & 7) + ((lane & 16) >> 1);
    int b_un  = (lane & 8) >> 3;

    #define LOAD_CHUNK(s, ci) do {                                            \
        int k0e = (ci) * KCH;                                                 \
        uint32_t db = sb + (s) * STAGE_BYTES;                                 \
        _Pragma("unroll")                                                     \
        for (int q = 0; q < 4; ++q) {                                         \
            int r = cr + q * 32;                                              \
            uint32_t d = db + r * 128 + ((cu ^ (r & 7)) << 4);                \
            size_t eA = (size_t)(row0 + r) * HH + k0e + cu * 8;               \
            size_t eB = (size_t)(col0 + r) * HH + k0e + cu * 8;               \
            CP16(d,                 (const char*)(Ahi + eA));                 \
            CP16(d + MAT_BYTES,     (const char*)(Alo + eA));                 \
            CP16(d + 2 * MAT_BYTES, (const char*)(Bhi + eB));                 \
            CP16(d + 3 * MAT_BYTES, (const char*)(Blo + eB));                 \
        }                                                                     \
        CP_COMMIT();                                                          \
    } while (0)

    LOAD_CHUNK(0, 0);

    for (int i = 0; i < NCHUNK; ++i) {
        if (i < NCHUNK - 1) { LOAD_CHUNK((i + 1) & 1, i + 1); CP_WAIT(1); }
        else                { CP_WAIT(0); }
        __syncthreads();

        uint32_t base = sb + (i & 1) * STAGE_BYTES;
        #pragma unroll
        for (int kk = 0; kk < KCH; kk += 16) {
            uint32_t ah[4][4], al[4][4], bh[4][2], bl[4][2];
            #pragma unroll
            for (int m = 0; m < 4; ++m) {
                int r = wr * 64 + m * 16 + a_row;
                int un = (kk >> 3) + a_un;
                uint32_t off = base + r * 128 + ((un ^ (r & 7)) << 4);
                LDM4(ah[m], off);
                LDM4(al[m], off + MAT_BYTES);
            }
            #pragma unroll
            for (int jp = 0; jp < 2; ++jp) {
                int r = wc * 32 + jp * 16 + b_row;
                int un = (kk >> 3) + b_un;
                uint32_t off = base + 2 * MAT_BYTES + r * 128 + ((un ^ (r & 7)) << 4);
                uint32_t t0[4], t1[4];
                LDM4(t0, off);
                LDM4(t1, off + MAT_BYTES);
                bh[2*jp][0] = t0[0]; bh[2*jp][1] = t0[1];
                bh[2*jp+1][0] = t0[2]; bh[2*jp+1][1] = t0[3];
                bl[2*jp][0] = t1[0]; bl[2*jp][1] = t1[1];
                bl[2*jp+1][0] = t1[2]; bl[2*jp+1][1] = t1[3];
            }
            #pragma unroll
            for (int m = 0; m < 4; ++m)
                #pragma unroll
                for (int j = 0; j < 4; ++j) {
                    MMA(acc[m][j], ah[m], bh[j]);
                    MMA(acc[m][j], ah[m], bl[j]);
                    MMA(acc[m][j], al[m], bh[j]);
                }
        }
        __syncthreads();
    }

    // ---- epilogue: registers -> global (fused bias / relu / mix) ----
    int tr = lane >> 2;
    int tc = (lane & 3) * 2;
    #pragma unroll
    for (int m = 0; m < 4; ++m) {
        #pragma unroll
        for (int half = 0; half < 2; ++half) {
            int row = row0 + wr * 64 + m * 16 + half * 8 + tr;
            float msk = 0.f;
            if (MODE == 1) msk = (mixu[row] < P_MIX_C) ? 1.f : 0.f;
            #pragma unroll
            for (int j = 0; j < 4; ++j) {
                int col = col0 + wc * 32 + j * 8 + tc;
                float v0 = acc[m][j][half * 2 + 0] + bias[col];
                float v1 = acc[m][j][half * 2 + 1] + bias[col + 1];
                size_t idx = (size_t)row * HH + col;
                if (MODE == 0) {
                    v0 = fmaxf(v0, 0.f); v1 = fmaxf(v1, 0.f);
                    __nv_bfloat16 h0, l0, h1, l1;
                    split_bf16(v0, h0, l0);
                    split_bf16(v1, h1, l1);
                    *(uint32_t*)(yhi + idx) = pack2(h0, h1);
                    *(uint32_t*)(ylo + idx) = pack2(l0, l1);
                } else {
                    float2 fcv = make_float2(v0, v1);
                    *(float2*)(fcout + idx) = fcv;
                    float2 bm = fcv;
                    if (msk != 0.f) bm = *(const float2*)(bert + idx);
                    *(float2*)(outbm + idx) = bm;
                }
            }
        }
    }
}

// ---------------------------------------------------------------------------
extern "C" void kernel_launch(void* const* d_in, const int* in_sizes, int n_in,
                              void* d_out, int out_size) {
    const float* hs      = (const float*)d_in[0];
    const int*   lengths = (const int*)  d_in[1];
    const float* W1      = (const float*)d_in[2];
    const float* b1      = (const float*)d_in[3];
    const float* W2      = (const float*)d_in[4];
    const float* b2      = (const float*)d_in[5];
    const float* bert    = (const float*)d_in[6];
    const float* mixu    = (const float*)d_in[7];
    float* out = (float*)d_out;

    __nv_bfloat16 *sahi, *salo, *y1hi, *y1lo, *w1h, *w1l, *w2h, *w2l;
    cudaGetSymbolAddress((void**)&sahi, g_sa_hi);
    cudaGetSymbolAddress((void**)&salo, g_sa_lo);
    cudaGetSymbolAddress((void**)&y1hi, g_y1_hi);
    cudaGetSymbolAddress((void**)&y1lo, g_y1_lo);
    cudaGetSymbolAddress((void**)&w1h, g_w1t_hi);
    cudaGetSymbolAddress((void**)&w1l, g_w1t_lo);
    cudaGetSymbolAddress((void**)&w2h, g_w2t_hi);
    cudaGetSymbolAddress((void**)&w2l, g_w2t_lo);

    cudaFuncSetAttribute(gemm_hmma<0>, cudaFuncAttributeMaxDynamicSharedMemorySize, SMEM_SZ);
    cudaFuncSetAttribute(gemm_hmma<1>, cudaFuncAttributeMaxDynamicSharedMemorySize, SMEM_SZ);

    alpha_kernel<<<BB, 256>>>(hs, lengths);
    nhat_kernel<<<1, 32>>>(out + NHAT_OFF);
    wtrans_kernel<<<dim3(24, 24), dim3(32, 8)>>>(W1, w1h, w1l, HM1);
    wtrans_kernel<<<dim3(24, 24), dim3(32, 8)>>>(W2, w2h, w2l, HH);
    cif_scan_kernel<<<dim3(3, BB), 256>>>(hs);

    gemm_hmma<0><<<dim3(6, 100), 256, SMEM_SZ>>>(
        sahi, salo, w1h, w1l, b1, y1hi, y1lo,
        nullptr, nullptr, nullptr, nullptr);
    gemm_hmma<1><<<dim3(6, 100), 256, SMEM_SZ>>>(
        y1hi, y1lo, w2h, w2l, b2, nullptr, nullptr,
        out /*bert_mixing*/, out + FC_OFF /*fc*/, bert, mixu);
}

// round 4
// speedup vs baseline: 2.8507x; 1.0195x over previous
#include <cuda_runtime.h>
#include <cuda_bf16.h>
#include <math.h>
#include <stdint.h>

#define BB 32
#define TT 1500
#define HH 768
#define HM1 767
#define LQ 400
#define MM (BB*TT/TT*LQ)           /* keep arithmetic simple below */
#undef MM
#define MM (BB*LQ)                 /* 12800 */
#define FC_OFF ((size_t)MM*HH)
#define NHAT_OFF ((size_t)2*MM*HH)
#define P_MIX_C 0.15f

// ---------------- scratch (__device__ globals, no allocs) ------------------
__device__ float g_scale[BB];
__device__ float g_nhat_part[BB];
__device__ __nv_bfloat16 g_sa_hi[(size_t)MM * HH];
__device__ __nv_bfloat16 g_sa_lo[(size_t)MM * HH];
__device__ __nv_bfloat16 g_y1_hi[(size_t)MM * HH];
__device__ __nv_bfloat16 g_y1_lo[(size_t)MM * HH];
__device__ __nv_bfloat16 g_w1t_hi[(size_t)HH * HH];
__device__ __nv_bfloat16 g_w1t_lo[(size_t)HH * HH];
__device__ __nv_bfloat16 g_w2t_hi[(size_t)HH * HH];
__device__ __nv_bfloat16 g_w2t_lo[(size_t)HH * HH];

// ---------------- helpers --------------------------------------------------
__device__ __forceinline__ uint32_t smem_u32(const void* p) {
    uint32_t a;
    asm("{ .reg .u64 t; cvta.to.shared.u64 t, %1; cvt.u32.u64 %0, t; }"
        : "=r"(a) : "l"(p));
    return a;
}
__device__ __forceinline__ void split_bf16(float v, __nv_bfloat16& h, __nv_bfloat16& l) {
    h = __float2bfloat16(v);
    l = __float2bfloat16(v - __bfloat162float(h));
}
__device__ __forceinline__ uint32_t pack2(__nv_bfloat16 a, __nv_bfloat16 b) {
    return (uint32_t)__bfloat16_as_ushort(a) |
           ((uint32_t)__bfloat16_as_ushort(b) << 16);
}

#define CP16(d, s) \
    asm volatile("cp.async.cg.shared.global [%0], [%1], 16;" :: "r"(d), "l"(s))
#define CP_COMMIT() asm volatile("cp.async.commit_group;" ::: "memory")
#define CP_WAIT(n)  asm volatile("cp.async.wait_group %0;" :: "n"(n) : "memory")

#define LDM4(r, addr) \
    asm volatile("ldmatrix.sync.aligned.m8n8.x4.shared.b16 {%0,%1,%2,%3},[%4];" \
        : "=r"((r)[0]), "=r"((r)[1]), "=r"((r)[2]), "=r"((r)[3]) : "r"(addr))

#define MMA(d, a, b) \
    asm volatile("mma.sync.aligned.m16n8k16.row.col.f32.bf16.bf16.f32 " \
        "{%0,%1,%2,%3},{%4,%5,%6,%7},{%8,%9},{%0,%1,%2,%3};" \
        : "+f"((d)[0]), "+f"((d)[1]), "+f"((d)[2]), "+f"((d)[3]) \
        : "r"((a)[0]), "r"((a)[1]), "r"((a)[2]), "r"((a)[3]), \
          "r"((b)[0]), "r"((b)[1]))

// ---------------------------------------------------------------------------
// Kernel 1: per-batch alpha sum, scale, n_hat partial
// ---------------------------------------------------------------------------
__global__ void alpha_kernel(const float* __restrict__ hs,
                             const int* __restrict__ lengths) {
    int b = blockIdx.x;
    const float* base = hs + (size_t)b * TT * HH + (HH - 1);
    float s = 0.f;
    for (int t = threadIdx.x; t < TT; t += blockDim.x)
        s += 1.f / (1.f + expf(-base[(size_t)t * HH]));
    __shared__ float red[256];
    red[threadIdx.x] = s;
    __syncthreads();
    for (int o = 128; o > 0; o >>= 1) {
        if (threadIdx.x < o) red[threadIdx.x] += red[threadIdx.x + o];
        __syncthreads();
    }
    if (threadIdx.x == 0) {
        float sum = red[0];
        int li = lengths[b];
        float tll = (float)(li < LQ ? li : LQ);
        g_scale[b] = tll / sum;
        float d = tll - sum;
        g_nhat_part[b] = d * d;
    }
}
__global__ void nhat_kernel(float* __restrict__ out) {
    float v = g_nhat_part[threadIdx.x];
    #pragma unroll
    for (int o = 16; o > 0; o >>= 1) v += __shfl_down_sync(0xffffffffu, v, o);
    if (threadIdx.x == 0) out[0] = v;
}

// ---------------------------------------------------------------------------
// Kernel 2: CIF scan -> hi/lo bf16 planes. Pad lane 767 -> zeros.
// ---------------------------------------------------------------------------
__global__ void cif_scan_kernel(const float* __restrict__ hs) {
    int b = blockIdx.y;
    int f = blockIdx.x * blockDim.x + threadIdx.x;   // 0..767
    __shared__ float s_alpha[LQ];
    float scale = g_scale[b];
    const float* hb = hs + (size_t)b * TT * HH;
    for (int t = threadIdx.x; t < LQ; t += blockDim.x)
        s_alpha[t] = scale / (1.f + expf(-hb[(size_t)t * HH + (HH - 1)]));
    __syncthreads();

    bool valid = (f < HM1);
    const float* hcol = hb + f;
    size_t obase = (size_t)b * LQ * HH + f;

    float a_r = 0.f, s_r = 0.f;
    float h = valid ? hcol[0] : 0.f;
    for (int t = 0; t < LQ; ++t) {
        float hn = valid ? hcol[(size_t)(t + 1) * HH] : 0.f;
        float a = s_alpha[t];
        float a_a = a + a_r;
        float rem = 1.0f - a_r;
        float s_a_nf = s_r + a * h;
        float s_a;
        if (a_a >= 1.0f) {
            float a_r_f = a - rem;
            s_a = s_r + rem * h;
            a_r = a_r_f;
            s_r = a_r_f * h;
        } else {
            a_r = a_a; s_a = s_a_nf; s_r = s_a_nf;
        }
        __nv_bfloat16 hi, lo;
        split_bf16(s_a, hi, lo);
        g_sa_hi[obase + (size_t)t * HH] = hi;
        g_sa_lo[obase + (size_t)t * HH] = lo;
        h = hn;
    }
}

// ---------------------------------------------------------------------------
// Kernel 3: W transpose + split: Wt[n][k] = split(W[k][n]), k>=Kvalid -> 0
// ---------------------------------------------------------------------------
__global__ void wtrans_kernel(const float* __restrict__ W,
                              __nv_bfloat16* __restrict__ Wt_hi,
                              __nv_bfloat16* __restrict__ Wt_lo, int Kvalid) {
    __shared__ float t[32][33];
    int n = blockIdx.x * 32 + threadIdx.x;
    #pragma unroll
    for (int j = 0; j < 32; j += 8) {
        int k = blockIdx.y * 32 + threadIdx.y + j;
        t[threadIdx.y + j][threadIdx.x] = (k < Kvalid) ? W[(size_t)k * HH + n] : 0.f;
    }
    __syncthreads();
    #pragma unroll
    for (int j = 0; j < 32; j += 8) {
        int nn = blockIdx.x * 32 + threadIdx.y + j;
        int kk = blockIdx.y * 32 + threadIdx.x;
        __nv_bfloat16 hi, lo;
        split_bf16(t[threadIdx.x][threadIdx.y + j], hi, lo);
        Wt_hi[(size_t)nn * HH + kk] = hi;
        Wt_lo[(size_t)nn * HH + kk] = lo;
    }
}

// ---------------------------------------------------------------------------
// Kernel 4: HMMA split-bf16 GEMM. CTA tile 128x128, 512 threads / 16 warps
// (4x4 grid, warp tile 32x32 -> 4 warps per SMSP for latency hiding).
// K chunks of 64, 2-stage cp.async pipeline, XOR-swizzled SMEM.
// MODE 0: y1 = relu(A@B^T+b) -> hi/lo planes. MODE 1: fc + bert_mixing.
// ---------------------------------------------------------------------------
#define KCH 64
#define NCHUNK (HH / KCH)            /* 12 */
#define MAT_BYTES 16384              /* 128 rows x 128B */
#define STAGE_BYTES (4 * MAT_BYTES)  /* 65536 */
#define SMEM_SZ (2 * STAGE_BYTES)    /* 131072 */

template <int MODE>
__global__ void __launch_bounds__(512, 1)
gemm_hmma(const __nv_bfloat16* __restrict__ Ahi, const __nv_bfloat16* __restrict__ Alo,
          const __nv_bfloat16* __restrict__ Bhi, const __nv_bfloat16* __restrict__ Blo,
          const float* __restrict__ bias,
          __nv_bfloat16* __restrict__ yhi, __nv_bfloat16* __restrict__ ylo,
          float* __restrict__ outbm, float* __restrict__ fcout,
          const float* __restrict__ bert, const float* __restrict__ mixu) {
    extern __shared__ char smem[];
    uint32_t sb = smem_u32(smem);
    int tid = threadIdx.x, lane = tid & 31, wid = tid >> 5;
    int row0 = blockIdx.y * 128, col0 = blockIdx.x * 128;
    int wr = wid >> 2, wc = wid & 3;     // warp tile: rows wr*32, cols wc*32

    float acc[2][4][4];
    #pragma unroll
    for (int i = 0; i < 2; ++i)
        #pragma unroll
        for (int j = 0; j < 4; ++j)
            #pragma unroll
            for (int d = 0; d < 4; ++d) acc[i][j][d] = 0.f;

    // copy indexing (per 16B unit): 512 threads cover 64 rows x 8 units
    int cr = tid >> 3, cu = tid & 7;

    // ldmatrix lane geometry (identical to validated R3 layout)
    int a_row = lane & 15;
    int a_un  = lane >> 4;
    int b_row = (lane & 7) + ((lane & 16) >> 1);
    int b_un  = (lane & 8) >> 3;

    #define LOAD_CHUNK(s, ci) do {                                            \
        int k0e = (ci) * KCH;                                                 \
        uint32_t db = sb + (s) * STAGE_BYTES;                                 \
        _Pragma("unroll")                                                     \
        for (int q = 0; q < 2; ++q) {                                         \
            int r = cr + q * 64;                                              \
            uint32_t d = db + r * 128 + ((cu ^ (r & 7)) << 4);                \
            size_t eA = (size_t)(row0 + r) * HH + k0e + cu * 8;               \
            size_t eB = (size_t)(col0 + r) * HH + k0e + cu * 8;               \
            CP16(d,                 (const char*)(Ahi + eA));                 \
            CP16(d + MAT_BYTES,     (const char*)(Alo + eA));                 \
            CP16(d + 2 * MAT_BYTES, (const char*)(Bhi + eB));                 \
            CP16(d + 3 * MAT_BYTES, (const char*)(Blo + eB));                 \
        }                                                                     \
        CP_COMMIT();                                                          \
    } while (0)

    LOAD_CHUNK(0, 0);

    for (int i = 0; i < NCHUNK; ++i) {
        if (i < NCHUNK - 1) { LOAD_CHUNK((i + 1) & 1, i + 1); CP_WAIT(1); }
        else                { CP_WAIT(0); }
        __syncthreads();

        uint32_t base = sb + (i & 1) * STAGE_BYTES;
        #pragma unroll
        for (int kk = 0; kk < KCH; kk += 16) {
            uint32_t ah[2][4], al[2][4], bh[4][2], bl[4][2];
            #pragma unroll
            for (int m = 0; m < 2; ++m) {
                int r = wr * 32 + m * 16 + a_row;
                int un = (kk >> 3) + a_un;
                uint32_t off = base + r * 128 + ((un ^ (r & 7)) << 4);
                LDM4(ah[m], off);
                LDM4(al[m], off + MAT_BYTES);
            }
            #pragma unroll
            for (int jp = 0; jp < 2; ++jp) {
                int r = wc * 32 + jp * 16 + b_row;
                int un = (kk >> 3) + b_un;
                uint32_t off = base + 2 * MAT_BYTES + r * 128 + ((un ^ (r & 7)) << 4);
                uint32_t t0[4], t1[4];
                LDM4(t0, off);
                LDM4(t1, off + MAT_BYTES);
                bh[2*jp][0] = t0[0]; bh[2*jp][1] = t0[1];
                bh[2*jp+1][0] = t0[2]; bh[2*jp+1][1] = t0[3];
                bl[2*jp][0] = t1[0]; bl[2*jp][1] = t1[1];
                bl[2*jp+1][0] = t1[2]; bl[2*jp+1][1] = t1[3];
            }
            #pragma unroll
            for (int m = 0; m < 2; ++m)
                #pragma unroll
                for (int j = 0; j < 4; ++j) {
                    MMA(acc[m][j], ah[m], bh[j]);
                    MMA(acc[m][j], ah[m], bl[j]);
                    MMA(acc[m][j], al[m], bh[j]);
                }
        }
        __syncthreads();
    }

    // ---- epilogue: registers -> global (fused bias / relu / mix) ----
    int tr = lane >> 2;
    int tc = (lane & 3) * 2;
    #pragma unroll
    for (int m = 0; m < 2; ++m) {
        #pragma unroll
        for (int half = 0; half < 2; ++half) {
            int row = row0 + wr * 32 + m * 16 + half * 8 + tr;
            float msk = 0.f;
            if (MODE == 1) msk = (mixu[row] < P_MIX_C) ? 1.f : 0.f;
            #pragma unroll
            for (int j = 0; j < 4; ++j) {
                int col = col0 + wc * 32 + j * 8 + tc;
                float v0 = acc[m][j][half * 2 + 0] + bias[col];
                float v1 = acc[m][j][half * 2 + 1] + bias[col + 1];
                size_t idx = (size_t)row * HH + col;
                if (MODE == 0) {
                    v0 = fmaxf(v0, 0.f); v1 = fmaxf(v1, 0.f);
                    __nv_bfloat16 h0, l0, h1, l1;
                    split_bf16(v0, h0, l0);
                    split_bf16(v1, h1, l1);
                    *(uint32_t*)(yhi + idx) = pack2(h0, h1);
                    *(uint32_t*)(ylo + idx) = pack2(l0, l1);
                } else {
                    float2 fcv = make_float2(v0, v1);
                    *(float2*)(fcout + idx) = fcv;
                    float2 bm = fcv;
                    if (msk != 0.f) bm = *(const float2*)(bert + idx);
                    *(float2*)(outbm + idx) = bm;
                }
            }
        }
    }
}

// ---------------------------------------------------------------------------
extern "C" void kernel_launch(void* const* d_in, const int* in_sizes, int n_in,
                              void* d_out, int out_size) {
    const float* hs      = (const float*)d_in[0];
    const int*   lengths = (const int*)  d_in[1];
    const float* W1      = (const float*)d_in[2];
    const float* b1      = (const float*)d_in[3];
    const float* W2      = (const float*)d_in[4];
    const float* b2      = (const float*)d_in[5];
    const float* bert    = (const float*)d_in[6];
    const float* mixu    = (const float*)d_in[7];
    float* out = (float*)d_out;

    __nv_bfloat16 *sahi, *salo, *y1hi, *y1lo, *w1h, *w1l, *w2h, *w2l;
    cudaGetSymbolAddress((void**)&sahi, g_sa_hi);
    cudaGetSymbolAddress((void**)&salo, g_sa_lo);
    cudaGetSymbolAddress((void**)&y1hi, g_y1_hi);
    cudaGetSymbolAddress((void**)&y1lo, g_y1_lo);
    cudaGetSymbolAddress((void**)&w1h, g_w1t_hi);
    cudaGetSymbolAddress((void**)&w1l, g_w1t_lo);
    cudaGetSymbolAddress((void**)&w2h, g_w2t_hi);
    cudaGetSymbolAddress((void**)&w2l, g_w2t_lo);

    cudaFuncSetAttribute(gemm_hmma<0>, cudaFuncAttributeMaxDynamicSharedMemorySize, SMEM_SZ);
    cudaFuncSetAttribute(gemm_hmma<1>, cudaFuncAttributeMaxDynamicSharedMemorySize, SMEM_SZ);

    alpha_kernel<<<BB, 256>>>(hs, lengths);
    nhat_kernel<<<1, 32>>>(out + NHAT_OFF);
    wtrans_kernel<<<dim3(24, 24), dim3(32, 8)>>>(W1, w1h, w1l, HM1);
    wtrans_kernel<<<dim3(24, 24), dim3(32, 8)>>>(W2, w2h, w2l, HH);
    cif_scan_kernel<<<dim3(3, BB), 256>>>(hs);

    gemm_hmma<0><<<dim3(6, 100), 512, SMEM_SZ>>>(
        sahi, salo, w1h, w1l, b1, y1hi, y1lo,
        nullptr, nullptr, nullptr, nullptr);
    gemm_hmma<1><<<dim3(6, 100), 512, SMEM_SZ>>>(
        y1hi, y1lo, w2h, w2l, b2, nullptr, nullptr,
        out /*bert_mixing*/, out + FC_OFF /*fc*/, bert, mixu);
}